// round 14
// baseline (speedup 1.0000x reference)
#include <cuda_runtime.h>

// Fused conv1 -> conv2 -> SIFT128 -> linear -> softmax, one CTA/image.
// Round 14: R11/R13 base + conv2 weights moved const->SHARED (broadcast
// LDS.128/.64, floor 2) to break the half-rate constant-port serialization
// (LDC->LDC floor=8; 1728 warp-LDC/CTA was ~3.5k cyc/SMSP of hidden stall).
// conv1 keeps LDCU (only ~20/thread). 5 CTAs/SM retained (44.0KB smem).

__constant__ float c_b1[32];
__constant__ float c_b2[3];
__constant__ float c_bl[10];
// conv1 packed weights only: pair gp at gp*10, slots 0..8 = taps, 9 = pad
__constant__ __align__(16) float2 c_wpk[160];

// staging: [0,160) conv1 padded pairs; [160,736) conv2 padded groups
__device__ __align__(16) float2 g_wpk[736];

typedef unsigned long long u64;

__device__ __forceinline__ void fma2(u64& d, u64 a, u64 b) {
    asm("fma.rn.f32x2 %0, %1, %2, %0;" : "+l"(d) : "l"(a), "l"(b));
}
__device__ __forceinline__ u64 pk2(float lo, float hi) {
    u64 r; asm("mov.b64 %0, {%1, %2};" : "=l"(r) : "f"(lo), "f"(hi)); return r;
}
__device__ __forceinline__ float2 upk(u64 v) {
    float2 f; asm("mov.b64 {%0, %1}, %2;" : "=f"(f.x), "=f"(f.y) : "l"(v)); return f;
}

#define A1_CP   938                      // u64 per channel-pair (=10 mod 16)
#define A1_RB(r) ((r) * 36 + (((r) & 1) << 2))
#define XS_ROW  28                       // xspl u64 row stride

// shared layout (floats). SM_A2P ALIASES SM_A1P (a1 dead when a2p written).
#define SM_XSPL    0                     // 28 x 28 u64 splat pairs -> 1568
#define SM_A1P     1568                  // 4 cp x 938 u64 -> 7504 f
#define SM_A2P     SM_A1P                // 3 ch padded 26x26 -> 2028 (alias)
#define SM_CELLS   (SM_A1P + 7504)       // 384
#define SM_NORMS   (SM_CELLS + 384)      // 4
#define SM_LOGITS  (SM_NORMS + 4)        // 12
#define SM_W2      9472                  // conv2 weights: 576 u64 = 1152 f (16B aligned)
#define SM_FLOATS  (SM_W2 + 1152)        // 10624 floats = 42496 B

__global__ void pack_weights(const float* __restrict__ W1,
                             const float* __restrict__ W2)
{
    int i = threadIdx.x + blockIdx.x * blockDim.x;
    if (i < 160) {
        int gp = i / 10, k = i % 10;
        float2 v = make_float2(0.0f, 0.0f);
        if (k < 9)
            v = make_float2(W1[(2 * gp) * 9 + k], W1[(2 * gp + 1) * 9 + k]);
        g_wpk[i] = v;
    } else if (i < 736) {
        int j = i - 160;
        int t    = j & 3;
        int grp  = j >> 2;            // (oc*16+icp)*3+dy
        int dy   = grp % 3;
        int rest = grp / 3;           // oc*16+icp
        int icp  = rest & 15;
        int oc   = rest >> 4;
        float2 v = make_float2(0.0f, 0.0f);
        if (t < 3)
            v = make_float2(W2[oc * 288 + (2 * icp) * 9 + dy * 3 + t],
                            W2[oc * 288 + (2 * icp + 1) * 9 + dy * 3 + t]);
        g_wpk[i] = v;
    }
}

__global__ __launch_bounds__(256, 5)
void fused_sift_net(const float* __restrict__ x,
                    const float* __restrict__ Wl,
                    float* __restrict__ out)
{
    extern __shared__ float sm[];
    const int tid = threadIdx.x;
    const int img = blockIdx.x;

    // ---------------- Phase 0: splat image + stage conv2 weights -----------
    {
        const float4* xg = (const float4*)(x + (size_t)img * 784);
        float4* xs = (float4*)&sm[SM_XSPL];
        for (int i4 = tid; i4 < 196; i4 += 256) {
            float4 v = __ldg(&xg[i4]);
            int li = i4 * 4;
            int r = li / 28, c = li % 28;          // c multiple of 4
            int fi = (r * XS_ROW + c) >> 1;        // float4 index (16B aligned)
            xs[fi]     = make_float4(v.x, v.x, v.y, v.y);
            xs[fi + 1] = make_float4(v.z, v.z, v.w, v.w);
        }
        // conv2 weights: g_wpk[160..736) = 288 float4 -> smem
        const float4* gw = (const float4*)(g_wpk + 160);
        float4* w2s = (float4*)&sm[SM_W2];
        for (int i = tid; i < 288; i += 256) w2s[i] = __ldg(&gw[i]);
    }

    // conv2 persistent accumulators: 192 threads, 1 out-row x 3-px strip x 3 oc
    const int c2row = tid >> 3;          // 0..23 (valid when tid<192)
    const int c2xs  = (tid & 7) * 3;     // 0,3,...,21
    u64 acc[3][3];
    if (tid < 192) {
#pragma unroll
        for (int oc = 0; oc < 3; oc++) {
            u64 bp = pk2(c_b2[oc], 0.0f);
#pragma unroll
            for (int j = 0; j < 3; j++) acc[oc][j] = bp;
        }
    }
    const int c2b0 = A1_RB(c2row)     + c2xs;
    const int c2b1 = A1_RB(c2row + 1) + c2xs;
    const int c2b2 = A1_RB(c2row + 2) + c2xs;

    const u64* wpk1 = (const u64*)c_wpk;        // constant bank (conv1 only)
    const u64* w2s  = (const u64*)&sm[SM_W2];   // smem (conv2, broadcast LDS)
    const u64* xspl = (const u64*)&sm[SM_XSPL];
    u64* a1u = (u64*)&sm[SM_A1P];

    // conv1 task decode: pl minor (4 pl lanes share image addresses)
    const int c1pl   = tid & 3;
    const int c1tt   = tid >> 2;         // 0..51 valid
    const int c1row  = c1tt >> 1;
    const int c1half = c1tt & 1;

    // ---------------- Phases 1-2: 4 chunks of 8 channels (4 pairs) ---------
    for (int chunk = 0; chunk < 4; chunk++) {
        __syncthreads();

        // conv1: 208 tasks = 52 (row,half) x 4 pairs; LDCU.128 weights
        if (tid < 208) {
            int gp = chunk * 4 + c1pl;
            const u64* ws = wpk1 + gp * 10;
            ulonglong2 q0 = *(const ulonglong2*)(ws);
            ulonglong2 q1 = *(const ulonglong2*)(ws + 2);
            ulonglong2 q2 = *(const ulonglong2*)(ws + 4);
            ulonglong2 q3 = *(const ulonglong2*)(ws + 6);
            u64 w8 = ws[8];
            u64 w0 = q0.x, w1 = q0.y, w2 = q1.x, w3 = q1.y;
            u64 w4 = q2.x, w5 = q2.y, w6 = q3.x, w7 = q3.y;
            u64 bp = pk2(c_b1[2 * gp], c_b1[2 * gp + 1]);
            const u64* xr = xspl + c1row * XS_ROW + c1half * 13;
            u64 t00 = xr[0],  t01 = xr[1];
            u64 t10 = xr[XS_ROW],     t11 = xr[XS_ROW + 1];
            u64 t20 = xr[2 * XS_ROW], t21 = xr[2 * XS_ROW + 1];
            float2* o = (float2*)(a1u + c1pl * A1_CP + A1_RB(c1row)) + c1half * 13;
#pragma unroll
            for (int s = 0; s < 13; s++) {
                u64 n0 = xr[s + 2];
                u64 n1 = xr[s + XS_ROW + 2];
                u64 n2 = xr[s + 2 * XS_ROW + 2];
                u64 a = bp;
                fma2(a, t00, w0); fma2(a, t01, w1); fma2(a, n0, w2);
                fma2(a, t10, w3); fma2(a, t11, w4); fma2(a, n1, w5);
                fma2(a, t20, w6); fma2(a, t21, w7); fma2(a, n2, w8);
                float2 f = upk(a);
                o[s] = make_float2(fmaxf(f.x, 0.0f), fmaxf(f.y, 0.0f));
                t00 = t01; t01 = n0;
                t10 = t11; t11 = n1;
                t20 = t21; t21 = n2;
            }
        }
        __syncthreads();

        // conv2: 4 icp; conflict-free act LDS, broadcast smem weight LDS
        if (tid < 192) {
#pragma unroll
            for (int icp = 0; icp < 4; icp++) {
                const u64* cb = a1u + icp * A1_CP;
                int gicp = chunk * 4 + icp;
#pragma unroll
                for (int dy = 0; dy < 3; dy++) {
                    const u64* ap = cb + (dy == 0 ? c2b0 : (dy == 1 ? c2b1 : c2b2));
                    u64 v0 = ap[0];
                    u64 v1 = ap[1];
                    u64 v2 = ap[2];
                    u64 v3 = ap[3];
                    u64 v4 = ap[4];
#pragma unroll
                    for (int oc = 0; oc < 3; oc++) {
                        const u64* wo = w2s + ((oc * 16 + gicp) * 3 + dy) * 4;
                        ulonglong2 wab = *(const ulonglong2*)wo;
                        u64 wa = wab.x, wb = wab.y, wc = wo[2];
                        fma2(acc[oc][0], v0, wa);
                        fma2(acc[oc][1], v1, wa);
                        fma2(acc[oc][2], v2, wa);
                        fma2(acc[oc][0], v1, wb);
                        fma2(acc[oc][1], v2, wb);
                        fma2(acc[oc][2], v3, wb);
                        fma2(acc[oc][0], v2, wc);
                        fma2(acc[oc][1], v3, wc);
                        fma2(acc[oc][2], v4, wc);
                    }
                }
            }
        }
    }

    // a1 is now dead (results live in acc registers). Re-use it for a2p:
    __syncthreads();
    for (int i = tid; i < 2028; i += 256) sm[SM_A2P + i] = 0.0f;
    __syncthreads();

    // conv2 outputs -> padded tile (scalar = lo + hi)
    if (tid < 192) {
#pragma unroll
        for (int oc = 0; oc < 3; oc++) {
            float* dst = &sm[SM_A2P + oc * 676 + (c2row + 1) * 26 + (c2xs + 1)];
#pragma unroll
            for (int j = 0; j < 3; j++) {
                float2 f = upk(acc[oc][j]);
                dst[j] = f.x + f.y;
            }
        }
    }
    __syncthreads();

    // ---------------- Phase 3: SIFT, register histograms --------------------
    if (tid < 192) {
        const float CS[8] = { 0.92387953f,  0.38268343f, -0.38268343f, -0.92387953f,
                             -0.92387953f, -0.38268343f,  0.38268343f,  0.92387953f};
        const float SN[8] = { 0.38268343f,  0.92387953f,  0.92387953f,  0.38268343f,
                             -0.38268343f, -0.92387953f, -0.92387953f, -0.38268343f};
        int p    = tid / 64;
        int rem  = tid % 64;
        int cell = rem >> 2;
        int quad = rem & 3;
        int r0 = (cell >> 2) * 6 + (quad >> 1) * 3;
        int c0 = (cell & 3) * 6 + (quad & 1) * 3;
        const float* ap = &sm[SM_A2P + p * 676 + r0 * 26 + c0];
        float pt[5][5];
#pragma unroll
        for (int i = 0; i < 5; i++)
#pragma unroll
            for (int j = 0; j < 5; j++) pt[i][j] = ap[i * 26 + j];

        float hist[8] = {0,0,0,0,0,0,0,0};
#pragma unroll
        for (int i = 0; i < 3; i++) {
#pragma unroll
            for (int j = 0; j < 3; j++) {
                float Ix = (pt[i][j+2] - pt[i][j])
                         + 2.0f * (pt[i+1][j+2] - pt[i+1][j])
                         + (pt[i+2][j+2] - pt[i+2][j]);
                float Iy = (pt[i+2][j] - pt[i][j])
                         + 2.0f * (pt[i+2][j+1] - pt[i][j+1])
                         + (pt[i+2][j+2] - pt[i][j+2]);
                float mag = sqrtf(Ix * Ix + Iy * Iy + 1e-12f);
                float ck[8];
                float cmax = -1e30f;
#pragma unroll
                for (int k = 0; k < 8; k++) {
                    ck[k] = CS[k] * Ix + SN[k] * Iy;
                    cmax = fmaxf(cmax, ck[k]);
                }
#pragma unroll
                for (int k = 0; k < 8; k++)
                    hist[k] += (ck[k] == cmax) ? mag : 0.0f;
            }
        }
#pragma unroll
        for (int k = 0; k < 8; k++) {
            float v = hist[k];
            v += __shfl_xor_sync(0xffffffffu, v, 1);
            v += __shfl_xor_sync(0xffffffffu, v, 2);
            if (quad == 0)
                sm[SM_CELLS + p * 128 + k * 16 + cell] = v;
        }
    }
    __syncthreads();

    // ---------------- Phase 4: norms + pow 0.9 ------------------------------
    if (tid < 96) {
        int w = tid >> 5, lane = tid & 31;
        const float* cp = &sm[SM_CELLS + w * 128];
        float s = 0.0f;
#pragma unroll
        for (int j = 0; j < 4; j++) {
            float v = cp[lane + 32 * j];
            s = fmaf(v, v, s);
        }
#pragma unroll
        for (int d = 16; d; d >>= 1)
            s += __shfl_xor_sync(0xffffffffu, s, d);
        if (lane == 0) sm[SM_NORMS + w] = sqrtf(s);
    }
    __syncthreads();
    {
        int i = tid;
        if (i < 384) {
            float v = sm[SM_CELLS + i];
            float f = v / (sm[SM_NORMS + (i >> 7)] + 1e-8f);
            sm[SM_CELLS + i] = powf(f + 1e-8f, 0.9f);
        }
        i = tid + 256;
        if (i < 384) {
            float v = sm[SM_CELLS + i];
            float f = v / (sm[SM_NORMS + (i >> 7)] + 1e-8f);
            sm[SM_CELLS + i] = powf(f + 1e-8f, 0.9f);
        }
    }
    __syncthreads();

    // ---------------- Phase 5: 384x10 linear --------------------------------
    {
        int w = tid >> 5, lane = tid & 31;
#pragma unroll
        for (int rep = 0; rep < 2; rep++) {
            int o = w + rep * 8;
            if (o < 10) {
                float s = 0.0f;
                const float* wrow = Wl + o * 384;
                for (int i = lane; i < 384; i += 32)
                    s = fmaf(sm[SM_CELLS + i], __ldg(&wrow[i]), s);
#pragma unroll
                for (int d = 16; d; d >>= 1)
                    s += __shfl_xor_sync(0xffffffffu, s, d);
                if (lane == 0) sm[SM_LOGITS + o] = s + c_bl[o];
            }
        }
    }
    __syncthreads();

    // ---------------- Phase 6: relu + softmax -------------------------------
    if (tid < 32) {
        float v = (tid < 10) ? fmaxf(sm[SM_LOGITS + tid], 0.0f) : -1e30f;
        float m = v;
#pragma unroll
        for (int d = 16; d; d >>= 1)
            m = fmaxf(m, __shfl_xor_sync(0xffffffffu, m, d));
        float e = (tid < 10) ? expf(v - m) : 0.0f;
        float ssum = e;
#pragma unroll
        for (int d = 16; d; d >>= 1)
            ssum += __shfl_xor_sync(0xffffffffu, ssum, d);
        if (tid < 10) out[(size_t)img * 10 + tid] = e / ssum;
    }
}

extern "C" void kernel_launch(void* const* d_in, const int* in_sizes, int n_in,
                              void* d_out, int out_size)
{
    const float* x  = (const float*)d_in[0];
    const float* W1 = (const float*)d_in[1];
    const float* b1 = (const float*)d_in[2];
    const float* W2 = (const float*)d_in[3];
    const float* b2 = (const float*)d_in[4];
    const float* Wl = (const float*)d_in[5];
    const float* bl = (const float*)d_in[6];

    int nimg = in_sizes[0] / 784;

    cudaMemcpyToSymbolAsync(c_b1, b1, 32 * sizeof(float), 0, cudaMemcpyDeviceToDevice, 0);
    cudaMemcpyToSymbolAsync(c_b2, b2,  3 * sizeof(float), 0, cudaMemcpyDeviceToDevice, 0);
    cudaMemcpyToSymbolAsync(c_bl, bl, 10 * sizeof(float), 0, cudaMemcpyDeviceToDevice, 0);

    pack_weights<<<3, 256>>>(W1, W2);
    void* gsrc = nullptr;
    cudaGetSymbolAddress(&gsrc, g_wpk);
    // conv1 pairs only into the constant bank
    cudaMemcpyToSymbolAsync(c_wpk, gsrc, 160 * sizeof(float2), 0,
                            cudaMemcpyDeviceToDevice, 0);

    size_t smem = SM_FLOATS * sizeof(float);
    cudaFuncSetAttribute(fused_sift_net,
                         cudaFuncAttributeMaxDynamicSharedMemorySize, (int)smem);

    fused_sift_net<<<nimg, 256, smem>>>(x, Wl, (float*)d_out);
}

// round 15
// speedup vs baseline: 1.1807x; 1.1807x over previous
#include <cuda_runtime.h>

// Fused conv1 -> conv2 -> SIFT128 -> linear -> softmax, one CTA/image.
// Round 15: exact R11 conv core (proven 299.5us: const-bank weights,
// conflict-free a1, 5 CTAs/SM @48 regs) + border-only a2p zero merged with
// the interior write (saves ~1700 STS + 1 barrier) + all constants in ONE
// table/memcpy (fewer graph nodes, conv1 bias = single LDC.64).

// unified constant table (float2):
//   [0,144)   conv1 pairs: gp*9 + tap = (w_even, w_odd)
//   [144,576) conv2: (oc*16+icp)*9 + tap = (w_even, w_odd)
//   [576,592) b1 pairs ; [592,594) b2 (3 floats + pad) ; [594,599) bl ; 599 pad
__constant__ __align__(16) float2 c_wpk[600];

__device__ __align__(16) float2 g_wpk[600];

typedef unsigned long long u64;

__device__ __forceinline__ void fma2(u64& d, u64 a, u64 b) {
    asm("fma.rn.f32x2 %0, %1, %2, %0;" : "+l"(d) : "l"(a), "l"(b));
}
__device__ __forceinline__ u64 pk2(float lo, float hi) {
    u64 r; asm("mov.b64 %0, {%1, %2};" : "=l"(r) : "f"(lo), "f"(hi)); return r;
}
__device__ __forceinline__ float2 upk(u64 v) {
    float2 f; asm("mov.b64 {%0, %1}, %2;" : "=f"(f.x), "=f"(f.y) : "l"(v)); return f;
}

#define A1_CP   938                      // u64 per channel-pair (=10 mod 16)
#define A1_RB(r) ((r) * 36 + (((r) & 1) << 2))
#define XS_ROW  28                       // xspl u64 row stride

// shared layout (floats). SM_A2P ALIASES SM_A1P (a1 dead when a2p written).
#define SM_XSPL    0                     // 28 x 28 u64 splat pairs -> 1568
#define SM_A1P     1568                  // 4 cp x 938 u64 -> 7504 f
#define SM_A2P     SM_A1P                // 3 ch padded 26x26 -> 2028 (alias)
#define SM_CELLS   (SM_A1P + 7504)       // 384
#define SM_NORMS   (SM_CELLS + 384)      // 4
#define SM_LOGITS  (SM_NORMS + 4)        // 12
#define SM_FLOATS  (SM_LOGITS + 12)      // 9472 floats = 37888 B

__global__ void pack_weights(const float* __restrict__ W1,
                             const float* __restrict__ W2,
                             const float* __restrict__ b1,
                             const float* __restrict__ b2,
                             const float* __restrict__ bl)
{
    int i = threadIdx.x + blockIdx.x * blockDim.x;
    if (i < 144) {
        int p = i / 9, k = i % 9;
        g_wpk[i] = make_float2(W1[(2 * p) * 9 + k], W1[(2 * p + 1) * 9 + k]);
    } else if (i < 576) {
        int j = i - 144;
        int oc = j / 144, r = j % 144;
        int icp = r / 9, tap = r % 9;
        g_wpk[i] = make_float2(W2[oc * 288 + (2 * icp) * 9 + tap],
                               W2[oc * 288 + (2 * icp + 1) * 9 + tap]);
    } else if (i < 592) {
        int gp = i - 576;
        g_wpk[i] = make_float2(b1[2 * gp], b1[2 * gp + 1]);
    } else if (i == 592) {
        g_wpk[i] = make_float2(b2[0], b2[1]);
    } else if (i == 593) {
        g_wpk[i] = make_float2(b2[2], 0.0f);
    } else if (i < 599) {
        int k = i - 594;
        g_wpk[i] = make_float2(bl[2 * k], bl[2 * k + 1]);
    } else if (i == 599) {
        g_wpk[i] = make_float2(0.0f, 0.0f);
    }
}

__global__ __launch_bounds__(256, 5)
void fused_sift_net(const float* __restrict__ x,
                    const float* __restrict__ Wl,
                    float* __restrict__ out)
{
    extern __shared__ float sm[];
    const int tid = threadIdx.x;
    const int img = blockIdx.x;

    const u64* wpk1 = (const u64*)c_wpk;            // conv1 weights
    const u64* wpk2 = wpk1 + 144;                   // conv2 weights
    const u64* bias1 = wpk1 + 576;                  // b1 pairs
    const float* cfl = (const float*)c_wpk;         // scalar view
    // b2[oc] = cfl[1184+oc], bl[o] = cfl[1188+o]

    // ---------------- Phase 0: splat image ---------------------------------
    {
        const float4* xg = (const float4*)(x + (size_t)img * 784);
        float4* xs = (float4*)&sm[SM_XSPL];
        for (int i4 = tid; i4 < 196; i4 += 256) {
            float4 v = __ldg(&xg[i4]);
            int li = i4 * 4;
            int r = li / 28, c = li % 28;          // c multiple of 4
            int fi = (r * XS_ROW + c) >> 1;        // float4 index (16B aligned)
            xs[fi]     = make_float4(v.x, v.x, v.y, v.y);
            xs[fi + 1] = make_float4(v.z, v.z, v.w, v.w);
        }
    }

    // conv2 persistent accumulators: 192 threads, 1 out-row x 3-px strip x 3 oc
    const int c2row = tid >> 3;          // 0..23 (valid when tid<192)
    const int c2xs  = (tid & 7) * 3;     // 0,3,...,21
    u64 acc[3][3];
    if (tid < 192) {
#pragma unroll
        for (int oc = 0; oc < 3; oc++) {
            u64 bp = pk2(cfl[1184 + oc], 0.0f);
#pragma unroll
            for (int j = 0; j < 3; j++) acc[oc][j] = bp;
        }
    }
    const int c2b0 = A1_RB(c2row)     + c2xs;
    const int c2b1 = A1_RB(c2row + 1) + c2xs;
    const int c2b2 = A1_RB(c2row + 2) + c2xs;

    const u64* xspl = (const u64*)&sm[SM_XSPL];
    u64* a1u = (u64*)&sm[SM_A1P];

    // conv1 task decode: pl minor (4 pl lanes share image addresses)
    const int c1pl   = tid & 3;
    const int c1tt   = tid >> 2;         // 0..51 valid
    const int c1row  = c1tt >> 1;
    const int c1half = c1tt & 1;

    // ---------------- Phases 1-2: 4 chunks of 8 channels (4 pairs) ---------
    for (int chunk = 0; chunk < 4; chunk++) {
        __syncthreads();

        // conv1: 208 tasks = 52 (row,half) x 4 pairs
        if (tid < 208) {
            int gp = chunk * 4 + c1pl;
            const u64* ws = wpk1 + gp * 9;
            u64 w0 = ws[0], w1 = ws[1], w2 = ws[2];
            u64 w3 = ws[3], w4 = ws[4], w5 = ws[5];
            u64 w6 = ws[6], w7 = ws[7], w8 = ws[8];
            u64 bp = bias1[gp];
            const u64* xr = xspl + c1row * XS_ROW + c1half * 13;
            u64 t00 = xr[0],  t01 = xr[1];
            u64 t10 = xr[XS_ROW],     t11 = xr[XS_ROW + 1];
            u64 t20 = xr[2 * XS_ROW], t21 = xr[2 * XS_ROW + 1];
            float2* o = (float2*)(a1u + c1pl * A1_CP + A1_RB(c1row)) + c1half * 13;
#pragma unroll
            for (int s = 0; s < 13; s++) {
                u64 n0 = xr[s + 2];
                u64 n1 = xr[s + XS_ROW + 2];
                u64 n2 = xr[s + 2 * XS_ROW + 2];
                u64 a = bp;
                fma2(a, t00, w0); fma2(a, t01, w1); fma2(a, n0, w2);
                fma2(a, t10, w3); fma2(a, t11, w4); fma2(a, n1, w5);
                fma2(a, t20, w6); fma2(a, t21, w7); fma2(a, n2, w8);
                float2 f = upk(a);
                o[s] = make_float2(fmaxf(f.x, 0.0f), fmaxf(f.y, 0.0f));
                t00 = t01; t01 = n0;
                t10 = t11; t11 = n1;
                t20 = t21; t21 = n2;
            }
        }
        __syncthreads();

        // conv2: 4 input-channel pairs; conflict-free acts, const weights
        if (tid < 192) {
#pragma unroll
            for (int icp = 0; icp < 4; icp++) {
                const u64* cb = a1u + icp * A1_CP;
                int gicp = chunk * 4 + icp;
#pragma unroll
                for (int dy = 0; dy < 3; dy++) {
                    const u64* ap = cb + (dy == 0 ? c2b0 : (dy == 1 ? c2b1 : c2b2));
                    u64 v0 = ap[0];
                    u64 v1 = ap[1];
                    u64 v2 = ap[2];
                    u64 v3 = ap[3];
                    u64 v4 = ap[4];
#pragma unroll
                    for (int oc = 0; oc < 3; oc++) {
                        const u64* wo = wpk2 + (oc * 16 + gicp) * 9 + dy * 3;
                        u64 wa = wo[0], wb = wo[1], wc = wo[2];
                        fma2(acc[oc][0], v0, wa);
                        fma2(acc[oc][1], v1, wa);
                        fma2(acc[oc][2], v2, wa);
                        fma2(acc[oc][0], v1, wb);
                        fma2(acc[oc][1], v2, wb);
                        fma2(acc[oc][2], v3, wb);
                        fma2(acc[oc][0], v2, wc);
                        fma2(acc[oc][1], v3, wc);
                        fma2(acc[oc][2], v4, wc);
                    }
                }
            }
        }
    }

    // a1 dead (results in registers). Alias as a2p: zero BORDER only (the
    // 24x24 interior per channel is fully overwritten below) + write interior
    // in the SAME barrier region (disjoint addresses).
    __syncthreads();
    for (int i = tid; i < 300; i += 256) {
        int p = i / 100, j = i % 100;
        int r, c;
        if (j < 26)      { r = 0;          c = j; }
        else if (j < 52) { r = 25;         c = j - 26; }
        else if (j < 76) { r = j - 52 + 1; c = 0; }
        else             { r = j - 76 + 1; c = 25; }
        sm[SM_A2P + p * 676 + r * 26 + c] = 0.0f;
    }
    if (tid < 192) {
#pragma unroll
        for (int oc = 0; oc < 3; oc++) {
            float* dst = &sm[SM_A2P + oc * 676 + (c2row + 1) * 26 + (c2xs + 1)];
#pragma unroll
            for (int j = 0; j < 3; j++) {
                float2 f = upk(acc[oc][j]);
                dst[j] = f.x + f.y;
            }
        }
    }
    __syncthreads();

    // ---------------- Phase 3: SIFT, register histograms --------------------
    if (tid < 192) {
        const float CS[8] = { 0.92387953f,  0.38268343f, -0.38268343f, -0.92387953f,
                             -0.92387953f, -0.38268343f,  0.38268343f,  0.92387953f};
        const float SN[8] = { 0.38268343f,  0.92387953f,  0.92387953f,  0.38268343f,
                             -0.38268343f, -0.92387953f, -0.92387953f, -0.38268343f};
        int p    = tid / 64;
        int rem  = tid % 64;
        int cell = rem >> 2;
        int quad = rem & 3;
        int r0 = (cell >> 2) * 6 + (quad >> 1) * 3;
        int c0 = (cell & 3) * 6 + (quad & 1) * 3;
        const float* ap = &sm[SM_A2P + p * 676 + r0 * 26 + c0];
        float pt[5][5];
#pragma unroll
        for (int i = 0; i < 5; i++)
#pragma unroll
            for (int j = 0; j < 5; j++) pt[i][j] = ap[i * 26 + j];

        float hist[8] = {0,0,0,0,0,0,0,0};
#pragma unroll
        for (int i = 0; i < 3; i++) {
#pragma unroll
            for (int j = 0; j < 3; j++) {
                float Ix = (pt[i][j+2] - pt[i][j])
                         + 2.0f * (pt[i+1][j+2] - pt[i+1][j])
                         + (pt[i+2][j+2] - pt[i+2][j]);
                float Iy = (pt[i+2][j] - pt[i][j])
                         + 2.0f * (pt[i+2][j+1] - pt[i][j+1])
                         + (pt[i+2][j+2] - pt[i][j+2]);
                float mag = sqrtf(Ix * Ix + Iy * Iy + 1e-12f);
                float ck[8];
                float cmax = -1e30f;
#pragma unroll
                for (int k = 0; k < 8; k++) {
                    ck[k] = CS[k] * Ix + SN[k] * Iy;
                    cmax = fmaxf(cmax, ck[k]);
                }
#pragma unroll
                for (int k = 0; k < 8; k++)
                    hist[k] += (ck[k] == cmax) ? mag : 0.0f;
            }
        }
#pragma unroll
        for (int k = 0; k < 8; k++) {
            float v = hist[k];
            v += __shfl_xor_sync(0xffffffffu, v, 1);
            v += __shfl_xor_sync(0xffffffffu, v, 2);
            if (quad == 0)
                sm[SM_CELLS + p * 128 + k * 16 + cell] = v;
        }
    }
    __syncthreads();

    // ---------------- Phase 4: norms + pow 0.9 ------------------------------
    if (tid < 96) {
        int w = tid >> 5, lane = tid & 31;
        const float* cp = &sm[SM_CELLS + w * 128];
        float s = 0.0f;
#pragma unroll
        for (int j = 0; j < 4; j++) {
            float v = cp[lane + 32 * j];
            s = fmaf(v, v, s);
        }
#pragma unroll
        for (int d = 16; d; d >>= 1)
            s += __shfl_xor_sync(0xffffffffu, s, d);
        if (lane == 0) sm[SM_NORMS + w] = sqrtf(s);
    }
    __syncthreads();
    {
        int i = tid;
        if (i < 384) {
            float v = sm[SM_CELLS + i];
            float f = v / (sm[SM_NORMS + (i >> 7)] + 1e-8f);
            sm[SM_CELLS + i] = powf(f + 1e-8f, 0.9f);
        }
        i = tid + 256;
        if (i < 384) {
            float v = sm[SM_CELLS + i];
            float f = v / (sm[SM_NORMS + (i >> 7)] + 1e-8f);
            sm[SM_CELLS + i] = powf(f + 1e-8f, 0.9f);
        }
    }
    __syncthreads();

    // ---------------- Phase 5: 384x10 linear --------------------------------
    {
        int w = tid >> 5, lane = tid & 31;
#pragma unroll
        for (int rep = 0; rep < 2; rep++) {
            int o = w + rep * 8;
            if (o < 10) {
                float s = 0.0f;
                const float* wrow = Wl + o * 384;
                for (int i = lane; i < 384; i += 32)
                    s = fmaf(sm[SM_CELLS + i], __ldg(&wrow[i]), s);
#pragma unroll
                for (int d = 16; d; d >>= 1)
                    s += __shfl_xor_sync(0xffffffffu, s, d);
                if (lane == 0) sm[SM_LOGITS + o] = s + cfl[1188 + o];
            }
        }
    }
    __syncthreads();

    // ---------------- Phase 6: relu + softmax -------------------------------
    if (tid < 32) {
        float v = (tid < 10) ? fmaxf(sm[SM_LOGITS + tid], 0.0f) : -1e30f;
        float m = v;
#pragma unroll
        for (int d = 16; d; d >>= 1)
            m = fmaxf(m, __shfl_xor_sync(0xffffffffu, m, d));
        float e = (tid < 10) ? expf(v - m) : 0.0f;
        float ssum = e;
#pragma unroll
        for (int d = 16; d; d >>= 1)
            ssum += __shfl_xor_sync(0xffffffffu, ssum, d);
        if (tid < 10) out[(size_t)img * 10 + tid] = e / ssum;
    }
}

extern "C" void kernel_launch(void* const* d_in, const int* in_sizes, int n_in,
                              void* d_out, int out_size)
{
    const float* x  = (const float*)d_in[0];
    const float* W1 = (const float*)d_in[1];
    const float* b1 = (const float*)d_in[2];
    const float* W2 = (const float*)d_in[3];
    const float* b2 = (const float*)d_in[4];
    const float* Wl = (const float*)d_in[5];
    const float* bl = (const float*)d_in[6];

    int nimg = in_sizes[0] / 784;

    pack_weights<<<3, 256>>>(W1, W2, b1, b2, bl);
    void* gsrc = nullptr;
    cudaGetSymbolAddress(&gsrc, g_wpk);
    cudaMemcpyToSymbolAsync(c_wpk, gsrc, 600 * sizeof(float2), 0,
                            cudaMemcpyDeviceToDevice, 0);

    size_t smem = SM_FLOATS * sizeof(float);
    cudaFuncSetAttribute(fused_sift_net,
                         cudaFuncAttributeMaxDynamicSharedMemorySize, (int)smem);

    fused_sift_net<<<nimg, 256, smem>>>(x, Wl, (float*)d_out);
}

// round 16
// speedup vs baseline: 1.2125x; 1.0269x over previous
#include <cuda_runtime.h>

// Fused conv1 -> conv2 -> SIFT128 -> linear -> softmax, one CTA/image.
// Round 16: R15 (best: 299.1us) + fast-math epilogue: powf->__powf
// (MUFU.LG2/EX2, args in (0,1] so rel-err ~1e-6 << 1e-3 tol), expf->__expf,
// divides->__fdividef. Conv core untouched.

// unified constant table (float2):
//   [0,144)   conv1 pairs: gp*9 + tap = (w_even, w_odd)
//   [144,576) conv2: (oc*16+icp)*9 + tap = (w_even, w_odd)
//   [576,592) b1 pairs ; [592,594) b2 (3 floats + pad) ; [594,599) bl ; 599 pad
__constant__ __align__(16) float2 c_wpk[600];

__device__ __align__(16) float2 g_wpk[600];

typedef unsigned long long u64;

__device__ __forceinline__ void fma2(u64& d, u64 a, u64 b) {
    asm("fma.rn.f32x2 %0, %1, %2, %0;" : "+l"(d) : "l"(a), "l"(b));
}
__device__ __forceinline__ u64 pk2(float lo, float hi) {
    u64 r; asm("mov.b64 %0, {%1, %2};" : "=l"(r) : "f"(lo), "f"(hi)); return r;
}
__device__ __forceinline__ float2 upk(u64 v) {
    float2 f; asm("mov.b64 {%0, %1}, %2;" : "=f"(f.x), "=f"(f.y) : "l"(v)); return f;
}

#define A1_CP   938                      // u64 per channel-pair (=10 mod 16)
#define A1_RB(r) ((r) * 36 + (((r) & 1) << 2))
#define XS_ROW  28                       // xspl u64 row stride

// shared layout (floats). SM_A2P ALIASES SM_A1P (a1 dead when a2p written).
#define SM_XSPL    0                     // 28 x 28 u64 splat pairs -> 1568
#define SM_A1P     1568                  // 4 cp x 938 u64 -> 7504 f
#define SM_A2P     SM_A1P                // 3 ch padded 26x26 -> 2028 (alias)
#define SM_CELLS   (SM_A1P + 7504)       // 384
#define SM_NORMS   (SM_CELLS + 384)      // 4
#define SM_LOGITS  (SM_NORMS + 4)        // 12
#define SM_FLOATS  (SM_LOGITS + 12)      // 9472 floats = 37888 B

__global__ void pack_weights(const float* __restrict__ W1,
                             const float* __restrict__ W2,
                             const float* __restrict__ b1,
                             const float* __restrict__ b2,
                             const float* __restrict__ bl)
{
    int i = threadIdx.x + blockIdx.x * blockDim.x;
    if (i < 144) {
        int p = i / 9, k = i % 9;
        g_wpk[i] = make_float2(W1[(2 * p) * 9 + k], W1[(2 * p + 1) * 9 + k]);
    } else if (i < 576) {
        int j = i - 144;
        int oc = j / 144, r = j % 144;
        int icp = r / 9, tap = r % 9;
        g_wpk[i] = make_float2(W2[oc * 288 + (2 * icp) * 9 + tap],
                               W2[oc * 288 + (2 * icp + 1) * 9 + tap]);
    } else if (i < 592) {
        int gp = i - 576;
        g_wpk[i] = make_float2(b1[2 * gp], b1[2 * gp + 1]);
    } else if (i == 592) {
        g_wpk[i] = make_float2(b2[0], b2[1]);
    } else if (i == 593) {
        g_wpk[i] = make_float2(b2[2], 0.0f);
    } else if (i < 599) {
        int k = i - 594;
        g_wpk[i] = make_float2(bl[2 * k], bl[2 * k + 1]);
    } else if (i == 599) {
        g_wpk[i] = make_float2(0.0f, 0.0f);
    }
}

__global__ __launch_bounds__(256, 5)
void fused_sift_net(const float* __restrict__ x,
                    const float* __restrict__ Wl,
                    float* __restrict__ out)
{
    extern __shared__ float sm[];
    const int tid = threadIdx.x;
    const int img = blockIdx.x;

    const u64* wpk1 = (const u64*)c_wpk;            // conv1 weights
    const u64* wpk2 = wpk1 + 144;                   // conv2 weights
    const u64* bias1 = wpk1 + 576;                  // b1 pairs
    const float* cfl = (const float*)c_wpk;         // scalar view
    // b2[oc] = cfl[1184+oc], bl[o] = cfl[1188+o]

    // ---------------- Phase 0: splat image ---------------------------------
    {
        const float4* xg = (const float4*)(x + (size_t)img * 784);
        float4* xs = (float4*)&sm[SM_XSPL];
        for (int i4 = tid; i4 < 196; i4 += 256) {
            float4 v = __ldg(&xg[i4]);
            int li = i4 * 4;
            int r = li / 28, c = li % 28;          // c multiple of 4
            int fi = (r * XS_ROW + c) >> 1;        // float4 index (16B aligned)
            xs[fi]     = make_float4(v.x, v.x, v.y, v.y);
            xs[fi + 1] = make_float4(v.z, v.z, v.w, v.w);
        }
    }

    // conv2 persistent accumulators: 192 threads, 1 out-row x 3-px strip x 3 oc
    const int c2row = tid >> 3;          // 0..23 (valid when tid<192)
    const int c2xs  = (tid & 7) * 3;     // 0,3,...,21
    u64 acc[3][3];
    if (tid < 192) {
#pragma unroll
        for (int oc = 0; oc < 3; oc++) {
            u64 bp = pk2(cfl[1184 + oc], 0.0f);
#pragma unroll
            for (int j = 0; j < 3; j++) acc[oc][j] = bp;
        }
    }
    const int c2b0 = A1_RB(c2row)     + c2xs;
    const int c2b1 = A1_RB(c2row + 1) + c2xs;
    const int c2b2 = A1_RB(c2row + 2) + c2xs;

    const u64* xspl = (const u64*)&sm[SM_XSPL];
    u64* a1u = (u64*)&sm[SM_A1P];

    // conv1 task decode: pl minor (4 pl lanes share image addresses)
    const int c1pl   = tid & 3;
    const int c1tt   = tid >> 2;         // 0..51 valid
    const int c1row  = c1tt >> 1;
    const int c1half = c1tt & 1;

    // ---------------- Phases 1-2: 4 chunks of 8 channels (4 pairs) ---------
    for (int chunk = 0; chunk < 4; chunk++) {
        __syncthreads();

        // conv1: 208 tasks = 52 (row,half) x 4 pairs
        if (tid < 208) {
            int gp = chunk * 4 + c1pl;
            const u64* ws = wpk1 + gp * 9;
            u64 w0 = ws[0], w1 = ws[1], w2 = ws[2];
            u64 w3 = ws[3], w4 = ws[4], w5 = ws[5];
            u64 w6 = ws[6], w7 = ws[7], w8 = ws[8];
            u64 bp = bias1[gp];
            const u64* xr = xspl + c1row * XS_ROW + c1half * 13;
            u64 t00 = xr[0],  t01 = xr[1];
            u64 t10 = xr[XS_ROW],     t11 = xr[XS_ROW + 1];
            u64 t20 = xr[2 * XS_ROW], t21 = xr[2 * XS_ROW + 1];
            float2* o = (float2*)(a1u + c1pl * A1_CP + A1_RB(c1row)) + c1half * 13;
#pragma unroll
            for (int s = 0; s < 13; s++) {
                u64 n0 = xr[s + 2];
                u64 n1 = xr[s + XS_ROW + 2];
                u64 n2 = xr[s + 2 * XS_ROW + 2];
                u64 a = bp;
                fma2(a, t00, w0); fma2(a, t01, w1); fma2(a, n0, w2);
                fma2(a, t10, w3); fma2(a, t11, w4); fma2(a, n1, w5);
                fma2(a, t20, w6); fma2(a, t21, w7); fma2(a, n2, w8);
                float2 f = upk(a);
                o[s] = make_float2(fmaxf(f.x, 0.0f), fmaxf(f.y, 0.0f));
                t00 = t01; t01 = n0;
                t10 = t11; t11 = n1;
                t20 = t21; t21 = n2;
            }
        }
        __syncthreads();

        // conv2: 4 input-channel pairs; conflict-free acts, const weights
        if (tid < 192) {
#pragma unroll
            for (int icp = 0; icp < 4; icp++) {
                const u64* cb = a1u + icp * A1_CP;
                int gicp = chunk * 4 + icp;
#pragma unroll
                for (int dy = 0; dy < 3; dy++) {
                    const u64* ap = cb + (dy == 0 ? c2b0 : (dy == 1 ? c2b1 : c2b2));
                    u64 v0 = ap[0];
                    u64 v1 = ap[1];
                    u64 v2 = ap[2];
                    u64 v3 = ap[3];
                    u64 v4 = ap[4];
#pragma unroll
                    for (int oc = 0; oc < 3; oc++) {
                        const u64* wo = wpk2 + (oc * 16 + gicp) * 9 + dy * 3;
                        u64 wa = wo[0], wb = wo[1], wc = wo[2];
                        fma2(acc[oc][0], v0, wa);
                        fma2(acc[oc][1], v1, wa);
                        fma2(acc[oc][2], v2, wa);
                        fma2(acc[oc][0], v1, wb);
                        fma2(acc[oc][1], v2, wb);
                        fma2(acc[oc][2], v3, wb);
                        fma2(acc[oc][0], v2, wc);
                        fma2(acc[oc][1], v3, wc);
                        fma2(acc[oc][2], v4, wc);
                    }
                }
            }
        }
    }

    // a1 dead (results in registers). Alias as a2p: zero BORDER only + write
    // interior in the SAME barrier region (disjoint addresses).
    __syncthreads();
    for (int i = tid; i < 300; i += 256) {
        int p = i / 100, j = i % 100;
        int r, c;
        if (j < 26)      { r = 0;          c = j; }
        else if (j < 52) { r = 25;         c = j - 26; }
        else if (j < 76) { r = j - 52 + 1; c = 0; }
        else             { r = j - 76 + 1; c = 25; }
        sm[SM_A2P + p * 676 + r * 26 + c] = 0.0f;
    }
    if (tid < 192) {
#pragma unroll
        for (int oc = 0; oc < 3; oc++) {
            float* dst = &sm[SM_A2P + oc * 676 + (c2row + 1) * 26 + (c2xs + 1)];
#pragma unroll
            for (int j = 0; j < 3; j++) {
                float2 f = upk(acc[oc][j]);
                dst[j] = f.x + f.y;
            }
        }
    }
    __syncthreads();

    // ---------------- Phase 3: SIFT, register histograms --------------------
    if (tid < 192) {
        const float CS[8] = { 0.92387953f,  0.38268343f, -0.38268343f, -0.92387953f,
                             -0.92387953f, -0.38268343f,  0.38268343f,  0.92387953f};
        const float SN[8] = { 0.38268343f,  0.92387953f,  0.92387953f,  0.38268343f,
                             -0.38268343f, -0.92387953f, -0.92387953f, -0.38268343f};
        int p    = tid / 64;
        int rem  = tid % 64;
        int cell = rem >> 2;
        int quad = rem & 3;
        int r0 = (cell >> 2) * 6 + (quad >> 1) * 3;
        int c0 = (cell & 3) * 6 + (quad & 1) * 3;
        const float* ap = &sm[SM_A2P + p * 676 + r0 * 26 + c0];
        float pt[5][5];
#pragma unroll
        for (int i = 0; i < 5; i++)
#pragma unroll
            for (int j = 0; j < 5; j++) pt[i][j] = ap[i * 26 + j];

        float hist[8] = {0,0,0,0,0,0,0,0};
#pragma unroll
        for (int i = 0; i < 3; i++) {
#pragma unroll
            for (int j = 0; j < 3; j++) {
                float Ix = (pt[i][j+2] - pt[i][j])
                         + 2.0f * (pt[i+1][j+2] - pt[i+1][j])
                         + (pt[i+2][j+2] - pt[i+2][j]);
                float Iy = (pt[i+2][j] - pt[i][j])
                         + 2.0f * (pt[i+2][j+1] - pt[i][j+1])
                         + (pt[i+2][j+2] - pt[i][j+2]);
                float mag = sqrtf(Ix * Ix + Iy * Iy + 1e-12f);
                float ck[8];
                float cmax = -1e30f;
#pragma unroll
                for (int k = 0; k < 8; k++) {
                    ck[k] = CS[k] * Ix + SN[k] * Iy;
                    cmax = fmaxf(cmax, ck[k]);
                }
#pragma unroll
                for (int k = 0; k < 8; k++)
                    hist[k] += (ck[k] == cmax) ? mag : 0.0f;
            }
        }
#pragma unroll
        for (int k = 0; k < 8; k++) {
            float v = hist[k];
            v += __shfl_xor_sync(0xffffffffu, v, 1);
            v += __shfl_xor_sync(0xffffffffu, v, 2);
            if (quad == 0)
                sm[SM_CELLS + p * 128 + k * 16 + cell] = v;
        }
    }
    __syncthreads();

    // ---------------- Phase 4: norms + pow 0.9 (fast-math) -----------------
    if (tid < 96) {
        int w = tid >> 5, lane = tid & 31;
        const float* cp = &sm[SM_CELLS + w * 128];
        float s = 0.0f;
#pragma unroll
        for (int j = 0; j < 4; j++) {
            float v = cp[lane + 32 * j];
            s = fmaf(v, v, s);
        }
#pragma unroll
        for (int d = 16; d; d >>= 1)
            s += __shfl_xor_sync(0xffffffffu, s, d);
        if (lane == 0) sm[SM_NORMS + w] = sqrtf(s);
    }
    __syncthreads();
    {
        int i = tid;
        if (i < 384) {
            float v = sm[SM_CELLS + i];
            float f = __fdividef(v, sm[SM_NORMS + (i >> 7)] + 1e-8f);
            sm[SM_CELLS + i] = __powf(f + 1e-8f, 0.9f);
        }
        i = tid + 256;
        if (i < 384) {
            float v = sm[SM_CELLS + i];
            float f = __fdividef(v, sm[SM_NORMS + (i >> 7)] + 1e-8f);
            sm[SM_CELLS + i] = __powf(f + 1e-8f, 0.9f);
        }
    }
    __syncthreads();

    // ---------------- Phase 5: 384x10 linear --------------------------------
    {
        int w = tid >> 5, lane = tid & 31;
#pragma unroll
        for (int rep = 0; rep < 2; rep++) {
            int o = w + rep * 8;
            if (o < 10) {
                float s = 0.0f;
                const float* wrow = Wl + o * 384;
                for (int i = lane; i < 384; i += 32)
                    s = fmaf(sm[SM_CELLS + i], __ldg(&wrow[i]), s);
#pragma unroll
                for (int d = 16; d; d >>= 1)
                    s += __shfl_xor_sync(0xffffffffu, s, d);
                if (lane == 0) sm[SM_LOGITS + o] = s + cfl[1188 + o];
            }
        }
    }
    __syncthreads();

    // ---------------- Phase 6: relu + softmax (fast exp) --------------------
    if (tid < 32) {
        float v = (tid < 10) ? fmaxf(sm[SM_LOGITS + tid], 0.0f) : -1e30f;
        float m = v;
#pragma unroll
        for (int d = 16; d; d >>= 1)
            m = fmaxf(m, __shfl_xor_sync(0xffffffffu, m, d));
        float e = (tid < 10) ? __expf(v - m) : 0.0f;
        float ssum = e;
#pragma unroll
        for (int d = 16; d; d >>= 1)
            ssum += __shfl_xor_sync(0xffffffffu, ssum, d);
        if (tid < 10) out[(size_t)img * 10 + tid] = __fdividef(e, ssum);
    }
}

extern "C" void kernel_launch(void* const* d_in, const int* in_sizes, int n_in,
                              void* d_out, int out_size)
{
    const float* x  = (const float*)d_in[0];
    const float* W1 = (const float*)d_in[1];
    const float* b1 = (const float*)d_in[2];
    const float* W2 = (const float*)d_in[3];
    const float* b2 = (const float*)d_in[4];
    const float* Wl = (const float*)d_in[5];
    const float* bl = (const float*)d_in[6];

    int nimg = in_sizes[0] / 784;

    pack_weights<<<3, 256>>>(W1, W2, b1, b2, bl);
    void* gsrc = nullptr;
    cudaGetSymbolAddress(&gsrc, g_wpk);
    cudaMemcpyToSymbolAsync(c_wpk, gsrc, 600 * sizeof(float2), 0,
                            cudaMemcpyDeviceToDevice, 0);

    size_t smem = SM_FLOATS * sizeof(float);
    cudaFuncSetAttribute(fused_sift_net,
                         cudaFuncAttributeMaxDynamicSharedMemorySize, (int)smem);

    fused_sift_net<<<nimg, 256, smem>>>(x, Wl, (float*)d_out);
}